// round 10
// baseline (speedup 1.0000x reference)
#include <cuda_runtime.h>

// Problem shape: deformation_field [B=2, C=3, D=192, H=192, W=192] float32.
// grad_x = d/dD (stride H*W), grad_y = d/dH (stride W), grad_z = d/dW (stride 1).
// loss = 0.1 * ( mean(div^2) + mean(sqrt(cx^2+cy^2+cz^2+1e-8)) )
// div = gx(f0)+gy(f1)+gz(f2); cx = gz(f1)-gy(f2); cy = gx(f2)-gz(f0); cz = gy(f0)-gx(f1).
// jnp.gradient: interior 0.5*(f[i+1]-f[i-1]); edges one-sided f[1]-f[0] / f[N-1]-f[N-2].

#define DD 192
#define HH 192
#define WW 192
#define NB 2

constexpr int CS = DD * HH * WW;   // channel stride (floats)
constexpr int XS = HH * WW;        // D-axis stride
constexpr int Y_TILE = 8;
constexpr int XSEG = 12;           // D-planes marched per block (192/12 = 16 segments)
constexpr int BX = 48;             // w-chunks of 4 floats: 48*4 = 192
constexpr int NTHREADS = BX * Y_TILE;  // 384

__device__ double g_acc;

__global__ void gcl_zero_kernel() { g_acc = 0.0; }

__global__ void gcl_finalize_kernel(float* __restrict__ out) {
    const double N = (double)NB * (double)DD * (double)HH * (double)WW;
    out[0] = (float)(0.1 * (g_acc / N));
}

__global__ void __launch_bounds__(NTHREADS)
gcl_main_kernel(const float* __restrict__ f) {
    const int cx   = threadIdx.x;            // 0..47  (w-chunk)
    const int ty   = threadIdx.y;            // 0..7
    const int w0   = cx * 4;
    const int y    = blockIdx.y * Y_TILE + ty;
    const int xs   = blockIdx.x * XSEG;
    const int b    = blockIdx.z;
    const int tid  = ty * BX + cx;
    const int lane = tid & 31;
    const unsigned FULL = 0xffffffffu;

    // base pointer for this (b, y, w0); channel c, plane x at: fb + c*CS + x*XS
    const float* fb = f + (size_t)b * (3 * (size_t)CS) + (size_t)y * WW + w0;

    // Register ring of 3 D-planes, 3 channels, float4 each.
    float pm[3][4], pc[3][4], pp[3][4];
    {
        const int xm  = (xs > 0) ? xs - 1 : 0;          // unused at x==0 (edge formula)
        const int xp1 = (xs + 1 < DD) ? xs + 1 : DD - 1;
#pragma unroll
        for (int c = 0; c < 3; c++) {
            float4 a = *reinterpret_cast<const float4*>(fb + c * CS + xm  * XS);
            float4 q = *reinterpret_cast<const float4*>(fb + c * CS + xs  * XS);
            float4 r = *reinterpret_cast<const float4*>(fb + c * CS + xp1 * XS);
            pm[c][0] = a.x; pm[c][1] = a.y; pm[c][2] = a.z; pm[c][3] = a.w;
            pc[c][0] = q.x; pc[c][1] = q.y; pc[c][2] = q.z; pc[c][3] = q.w;
            pp[c][0] = r.x; pp[c][1] = r.y; pp[c][2] = r.z; pp[c][3] = r.w;
        }
    }

    const int ym = (y > 0) ? y - 1 : 0;
    const int yp = (y < HH - 1) ? y + 1 : HH - 1;
    const int dym = (ym - y) * WW;   // -192 or 0
    const int dyp = (yp - y) * WW;   // +192 or 0

    float sum = 0.0f;

    for (int i = 0; i < XSEG; i++) {
        const int x = xs + i;

        // Prefetch plane x+2 (clamped; clamp value is never used by formulas).
        const int xn = (x + 2 < DD) ? x + 2 : DD - 1;
        float nxt[3][4];
#pragma unroll
        for (int c = 0; c < 3; c++) {
            float4 t = *reinterpret_cast<const float4*>(fb + c * CS + xn * XS);
            nxt[c][0] = t.x; nxt[c][1] = t.y; nxt[c][2] = t.z; nxt[c][3] = t.w;
        }

        // H-axis neighbors of the current plane (mostly L1 hits: loaded as some
        // thread's center prefetch one march-step earlier).
        float ymv[3][4], ypv[3][4];
        {
            const float* px = fb + x * XS;
#pragma unroll
            for (int c = 0; c < 3; c++) {
                float4 a = *reinterpret_cast<const float4*>(px + c * CS + dym);
                float4 q = *reinterpret_cast<const float4*>(px + c * CS + dyp);
                ymv[c][0] = a.x; ymv[c][1] = a.y; ymv[c][2] = a.z; ymv[c][3] = a.w;
                ypv[c][0] = q.x; ypv[c][1] = q.y; ypv[c][2] = q.z; ypv[c][3] = q.w;
            }
        }

        // W-axis halo via warp shuffle; patch warp-boundary lanes with loads.
        float lo[3], hi[3];
#pragma unroll
        for (int c = 0; c < 3; c++) {
            lo[c] = __shfl_up_sync(FULL, pc[c][3], 1);
            hi[c] = __shfl_down_sync(FULL, pc[c][0], 1);
        }
        if (lane == 0 && cx > 0) {
            const float* px = fb + x * XS;
#pragma unroll
            for (int c = 0; c < 3; c++) lo[c] = px[c * CS - 1];
        }
        if (lane == 31 && cx < BX - 1) {
            const float* px = fb + x * XS;
#pragma unroll
            for (int c = 0; c < 3; c++) hi[c] = px[c * CS + 4];
        }

#pragma unroll
        for (int j = 0; j < 4; j++) {
            const int w = w0 + j;
            float gx[3], gy[3], gz[3];
#pragma unroll
            for (int c = 0; c < 3; c++) {
                // D-axis
                if (x == 0)            gx[c] = pp[c][j] - pc[c][j];
                else if (x == DD - 1)  gx[c] = pc[c][j] - pm[c][j];
                else                   gx[c] = 0.5f * (pp[c][j] - pm[c][j]);
                // H-axis
                if (y == 0)            gy[c] = ypv[c][j] - pc[c][j];
                else if (y == HH - 1)  gy[c] = pc[c][j] - ymv[c][j];
                else                   gy[c] = 0.5f * (ypv[c][j] - ymv[c][j]);
                // W-axis
                const float prev = (j > 0) ? pc[c][j - 1] : lo[c];
                const float next = (j < 3) ? pc[c][j + 1] : hi[c];
                if (w == 0)            gz[c] = pc[c][1] - pc[c][0];
                else if (w == WW - 1)  gz[c] = pc[c][3] - pc[c][2];
                else                   gz[c] = 0.5f * (next - prev);
            }
            const float dv  = gx[0] + gy[1] + gz[2];
            const float cxv = gz[1] - gy[2];
            const float cyv = gx[2] - gz[0];
            const float czv = gy[0] - gx[1];
            sum += dv * dv + sqrtf(cxv * cxv + cyv * cyv + czv * czv + 1e-8f);
        }

        // Rotate the register ring.
#pragma unroll
        for (int c = 0; c < 3; c++) {
#pragma unroll
            for (int k = 0; k < 4; k++) {
                pm[c][k] = pc[c][k];
                pc[c][k] = pp[c][k];
                pp[c][k] = nxt[c][k];
            }
        }
    }

    // Block reduction -> one double atomic per block.
#pragma unroll
    for (int o = 16; o > 0; o >>= 1)
        sum += __shfl_down_sync(FULL, sum, o);

    __shared__ float wsums[NTHREADS / 32];
    const int wid = tid >> 5;
    if (lane == 0) wsums[wid] = sum;
    __syncthreads();
    if (tid == 0) {
        float t = 0.0f;
#pragma unroll
        for (int k = 0; k < NTHREADS / 32; k++) t += wsums[k];
        atomicAdd(&g_acc, (double)t);
    }
}

extern "C" void kernel_launch(void* const* d_in, const int* in_sizes, int n_in,
                              void* d_out, int out_size) {
    const float* f = (const float*)d_in[0];
    float* out = (float*)d_out;
    (void)in_sizes; (void)n_in; (void)out_size;

    gcl_zero_kernel<<<1, 1>>>();
    dim3 grid(DD / XSEG, HH / Y_TILE, NB);   // 16 x 24 x 2 = 768 blocks
    dim3 block(BX, Y_TILE);                  // 48 x 8 = 384 threads
    gcl_main_kernel<<<grid, block>>>(f);
    gcl_finalize_kernel<<<1, 1>>>(out);
}

// round 11
// speedup vs baseline: 1.0439x; 1.0439x over previous
#include <cuda_runtime.h>

// Problem shape: deformation_field [B=2, C=3, D=192, H=192, W=192] float32.
// grad_x = d/dD (stride H*W), grad_y = d/dH (stride W), grad_z = d/dW (stride 1).
// loss = 0.1 * ( mean(div^2) + mean(sqrt(cx^2+cy^2+cz^2+1e-8)) )
// div = gx(f0)+gy(f1)+gz(f2); cx = gz(f1)-gy(f2); cy = gx(f2)-gz(f0); cz = gy(f0)-gx(f1).
// jnp.gradient: interior 0.5*(f[i+1]-f[i-1]); edges one-sided f[1]-f[0] / f[N-1]-f[N-2].

#define DD 192
#define HH 192
#define WW 192
#define NB 2

constexpr int CS = DD * HH * WW;   // channel stride (floats)
constexpr int XS = HH * WW;        // D-axis stride
constexpr int Y_TILE = 8;
constexpr int XSEG = 12;           // D-planes marched per block (192/12 = 16 segments)
constexpr int BX = 48;             // w-chunks of 4 floats: 48*4 = 192
constexpr int NTHREADS = BX * Y_TILE;  // 384

__device__ double g_acc;

__global__ void gcl_zero_kernel() { g_acc = 0.0; }

__global__ void gcl_finalize_kernel(float* __restrict__ out) {
    const double N = (double)NB * (double)DD * (double)HH * (double)WW;
    out[0] = (float)(0.1 * (g_acc / N));
}

__global__ void __launch_bounds__(NTHREADS)
gcl_main_kernel(const float* __restrict__ f) {
    const int cx   = threadIdx.x;            // 0..47  (w-chunk)
    const int ty   = threadIdx.y;            // 0..7
    const int w0   = cx * 4;
    const int y    = blockIdx.y * Y_TILE + ty;
    const int xs   = blockIdx.x * XSEG;
    const int b    = blockIdx.z;
    const int tid  = ty * BX + cx;
    const int lane = tid & 31;
    const unsigned FULL = 0xffffffffu;

    // base pointer for this (b, y, w0); channel c, plane x at: fb + c*CS + x*XS
    const float* fb = f + (size_t)b * (3 * (size_t)CS) + (size_t)y * WW + w0;

    // Register ring of 3 D-planes, 3 channels, float4 each.
    float pm[3][4], pc[3][4], pp[3][4];
    {
        const int xm  = (xs > 0) ? xs - 1 : 0;          // unused at x==0 (edge formula)
        const int xp1 = (xs + 1 < DD) ? xs + 1 : DD - 1;
#pragma unroll
        for (int c = 0; c < 3; c++) {
            float4 a = *reinterpret_cast<const float4*>(fb + c * CS + xm  * XS);
            float4 q = *reinterpret_cast<const float4*>(fb + c * CS + xs  * XS);
            float4 r = *reinterpret_cast<const float4*>(fb + c * CS + xp1 * XS);
            pm[c][0] = a.x; pm[c][1] = a.y; pm[c][2] = a.z; pm[c][3] = a.w;
            pc[c][0] = q.x; pc[c][1] = q.y; pc[c][2] = q.z; pc[c][3] = q.w;
            pp[c][0] = r.x; pp[c][1] = r.y; pp[c][2] = r.z; pp[c][3] = r.w;
        }
    }

    const int ym = (y > 0) ? y - 1 : 0;
    const int yp = (y < HH - 1) ? y + 1 : HH - 1;
    const int dym = (ym - y) * WW;   // -192 or 0
    const int dyp = (yp - y) * WW;   // +192 or 0

    float sum = 0.0f;

    for (int i = 0; i < XSEG; i++) {
        const int x = xs + i;

        // Prefetch plane x+2 (clamped; clamp value is never used by formulas).
        const int xn = (x + 2 < DD) ? x + 2 : DD - 1;
        float nxt[3][4];
#pragma unroll
        for (int c = 0; c < 3; c++) {
            float4 t = *reinterpret_cast<const float4*>(fb + c * CS + xn * XS);
            nxt[c][0] = t.x; nxt[c][1] = t.y; nxt[c][2] = t.z; nxt[c][3] = t.w;
        }

        // H-axis neighbors of the current plane (mostly L1 hits: loaded as some
        // thread's center prefetch one march-step earlier).
        float ymv[3][4], ypv[3][4];
        {
            const float* px = fb + x * XS;
#pragma unroll
            for (int c = 0; c < 3; c++) {
                float4 a = *reinterpret_cast<const float4*>(px + c * CS + dym);
                float4 q = *reinterpret_cast<const float4*>(px + c * CS + dyp);
                ymv[c][0] = a.x; ymv[c][1] = a.y; ymv[c][2] = a.z; ymv[c][3] = a.w;
                ypv[c][0] = q.x; ypv[c][1] = q.y; ypv[c][2] = q.z; ypv[c][3] = q.w;
            }
        }

        // W-axis halo via warp shuffle; patch warp-boundary lanes with loads.
        float lo[3], hi[3];
#pragma unroll
        for (int c = 0; c < 3; c++) {
            lo[c] = __shfl_up_sync(FULL, pc[c][3], 1);
            hi[c] = __shfl_down_sync(FULL, pc[c][0], 1);
        }
        if (lane == 0 && cx > 0) {
            const float* px = fb + x * XS;
#pragma unroll
            for (int c = 0; c < 3; c++) lo[c] = px[c * CS - 1];
        }
        if (lane == 31 && cx < BX - 1) {
            const float* px = fb + x * XS;
#pragma unroll
            for (int c = 0; c < 3; c++) hi[c] = px[c * CS + 4];
        }

#pragma unroll
        for (int j = 0; j < 4; j++) {
            const int w = w0 + j;
            float gx[3], gy[3], gz[3];
#pragma unroll
            for (int c = 0; c < 3; c++) {
                // D-axis
                if (x == 0)            gx[c] = pp[c][j] - pc[c][j];
                else if (x == DD - 1)  gx[c] = pc[c][j] - pm[c][j];
                else                   gx[c] = 0.5f * (pp[c][j] - pm[c][j]);
                // H-axis
                if (y == 0)            gy[c] = ypv[c][j] - pc[c][j];
                else if (y == HH - 1)  gy[c] = pc[c][j] - ymv[c][j];
                else                   gy[c] = 0.5f * (ypv[c][j] - ymv[c][j]);
                // W-axis
                const float prev = (j > 0) ? pc[c][j - 1] : lo[c];
                const float next = (j < 3) ? pc[c][j + 1] : hi[c];
                if (w == 0)            gz[c] = pc[c][1] - pc[c][0];
                else if (w == WW - 1)  gz[c] = pc[c][3] - pc[c][2];
                else                   gz[c] = 0.5f * (next - prev);
            }
            const float dv  = gx[0] + gy[1] + gz[2];
            const float cxv = gz[1] - gy[2];
            const float cyv = gx[2] - gz[0];
            const float czv = gy[0] - gx[1];
            sum += dv * dv + sqrtf(cxv * cxv + cyv * cyv + czv * czv + 1e-8f);
        }

        // Rotate the register ring.
#pragma unroll
        for (int c = 0; c < 3; c++) {
#pragma unroll
            for (int k = 0; k < 4; k++) {
                pm[c][k] = pc[c][k];
                pc[c][k] = pp[c][k];
                pp[c][k] = nxt[c][k];
            }
        }
    }

    // Block reduction -> one double atomic per block.
#pragma unroll
    for (int o = 16; o > 0; o >>= 1)
        sum += __shfl_down_sync(FULL, sum, o);

    __shared__ float wsums[NTHREADS / 32];
    const int wid = tid >> 5;
    if (lane == 0) wsums[wid] = sum;
    __syncthreads();
    if (tid == 0) {
        float t = 0.0f;
#pragma unroll
        for (int k = 0; k < NTHREADS / 32; k++) t += wsums[k];
        atomicAdd(&g_acc, (double)t);
    }
}

extern "C" void kernel_launch(void* const* d_in, const int* in_sizes, int n_in,
                              void* d_out, int out_size) {
    const float* f = (const float*)d_in[0];
    float* out = (float*)d_out;
    (void)in_sizes; (void)n_in; (void)out_size;

    gcl_zero_kernel<<<1, 1>>>();
    dim3 grid(DD / XSEG, HH / Y_TILE, NB);   // 16 x 24 x 2 = 768 blocks
    dim3 block(BX, Y_TILE);                  // 48 x 8 = 384 threads
    gcl_main_kernel<<<grid, block>>>(f);
    gcl_finalize_kernel<<<1, 1>>>(out);
}

// round 12
// speedup vs baseline: 1.0556x; 1.0112x over previous
#include <cuda_runtime.h>

// Problem shape: deformation_field [B=2, C=3, D=192, H=192, W=192] float32.
// grad_x = d/dD (stride H*W), grad_y = d/dH (stride W), grad_z = d/dW (stride 1).
// loss = 0.1 * ( mean(div^2) + mean(sqrt(cx^2+cy^2+cz^2+1e-8)) )
// div = gx(f0)+gy(f1)+gz(f2); cx = gz(f1)-gy(f2); cy = gx(f2)-gz(f0); cz = gy(f0)-gx(f1).
// jnp.gradient: interior 0.5*(f[i+1]-f[i-1]); edges one-sided f[1]-f[0] / f[N-1]-f[N-2].

#define DD 192
#define HH 192
#define WW 192
#define NB 2

constexpr int CS = DD * HH * WW;   // channel stride (floats)
constexpr int XS = HH * WW;        // D-axis stride
constexpr int Y_TILE = 8;
constexpr int XSEG = 12;           // D-planes marched per block (192/12 = 16 segments)
constexpr int BX = 48;             // w-chunks of 4 floats: 48*4 = 192
constexpr int NTHREADS = BX * Y_TILE;  // 384

__device__ double g_acc;

__global__ void gcl_zero_kernel() { g_acc = 0.0; }

__global__ void gcl_finalize_kernel(float* __restrict__ out) {
    const double N = (double)NB * (double)DD * (double)HH * (double)WW;
    out[0] = (float)(0.1 * (g_acc / N));
}

__global__ void __launch_bounds__(NTHREADS)
gcl_main_kernel(const float* __restrict__ f) {
    const int cx   = threadIdx.x;            // 0..47  (w-chunk)
    const int ty   = threadIdx.y;            // 0..7
    const int w0   = cx * 4;
    const int y    = blockIdx.y * Y_TILE + ty;
    const int xs   = blockIdx.x * XSEG;
    const int b    = blockIdx.z;
    const int tid  = ty * BX + cx;
    const int lane = tid & 31;
    const unsigned FULL = 0xffffffffu;

    // base pointer for this (b, y, w0); channel c, plane x at: fb + c*CS + x*XS
    const float* fb = f + (size_t)b * (3 * (size_t)CS) + (size_t)y * WW + w0;

    // Register ring of 3 D-planes, 3 channels, float4 each.
    float pm[3][4], pc[3][4], pp[3][4];
    {
        const int xm  = (xs > 0) ? xs - 1 : 0;          // unused at x==0 (edge formula)
        const int xp1 = (xs + 1 < DD) ? xs + 1 : DD - 1;
#pragma unroll
        for (int c = 0; c < 3; c++) {
            float4 a = *reinterpret_cast<const float4*>(fb + c * CS + xm  * XS);
            float4 q = *reinterpret_cast<const float4*>(fb + c * CS + xs  * XS);
            float4 r = *reinterpret_cast<const float4*>(fb + c * CS + xp1 * XS);
            pm[c][0] = a.x; pm[c][1] = a.y; pm[c][2] = a.z; pm[c][3] = a.w;
            pc[c][0] = q.x; pc[c][1] = q.y; pc[c][2] = q.z; pc[c][3] = q.w;
            pp[c][0] = r.x; pp[c][1] = r.y; pp[c][2] = r.z; pp[c][3] = r.w;
        }
    }

    const int ym = (y > 0) ? y - 1 : 0;
    const int yp = (y < HH - 1) ? y + 1 : HH - 1;
    const int dym = (ym - y) * WW;   // -192 or 0
    const int dyp = (yp - y) * WW;   // +192 or 0

    float sum = 0.0f;

    for (int i = 0; i < XSEG; i++) {
        const int x = xs + i;

        // Prefetch plane x+2 (clamped; clamp value is never used by formulas).
        const int xn = (x + 2 < DD) ? x + 2 : DD - 1;
        float nxt[3][4];
#pragma unroll
        for (int c = 0; c < 3; c++) {
            float4 t = *reinterpret_cast<const float4*>(fb + c * CS + xn * XS);
            nxt[c][0] = t.x; nxt[c][1] = t.y; nxt[c][2] = t.z; nxt[c][3] = t.w;
        }

        // H-axis neighbors of the current plane (mostly L1 hits: loaded as some
        // thread's center prefetch one march-step earlier).
        float ymv[3][4], ypv[3][4];
        {
            const float* px = fb + x * XS;
#pragma unroll
            for (int c = 0; c < 3; c++) {
                float4 a = *reinterpret_cast<const float4*>(px + c * CS + dym);
                float4 q = *reinterpret_cast<const float4*>(px + c * CS + dyp);
                ymv[c][0] = a.x; ymv[c][1] = a.y; ymv[c][2] = a.z; ymv[c][3] = a.w;
                ypv[c][0] = q.x; ypv[c][1] = q.y; ypv[c][2] = q.z; ypv[c][3] = q.w;
            }
        }

        // W-axis halo via warp shuffle; patch warp-boundary lanes with loads.
        float lo[3], hi[3];
#pragma unroll
        for (int c = 0; c < 3; c++) {
            lo[c] = __shfl_up_sync(FULL, pc[c][3], 1);
            hi[c] = __shfl_down_sync(FULL, pc[c][0], 1);
        }
        if (lane == 0 && cx > 0) {
            const float* px = fb + x * XS;
#pragma unroll
            for (int c = 0; c < 3; c++) lo[c] = px[c * CS - 1];
        }
        if (lane == 31 && cx < BX - 1) {
            const float* px = fb + x * XS;
#pragma unroll
            for (int c = 0; c < 3; c++) hi[c] = px[c * CS + 4];
        }

#pragma unroll
        for (int j = 0; j < 4; j++) {
            const int w = w0 + j;
            float gx[3], gy[3], gz[3];
#pragma unroll
            for (int c = 0; c < 3; c++) {
                // D-axis
                if (x == 0)            gx[c] = pp[c][j] - pc[c][j];
                else if (x == DD - 1)  gx[c] = pc[c][j] - pm[c][j];
                else                   gx[c] = 0.5f * (pp[c][j] - pm[c][j]);
                // H-axis
                if (y == 0)            gy[c] = ypv[c][j] - pc[c][j];
                else if (y == HH - 1)  gy[c] = pc[c][j] - ymv[c][j];
                else                   gy[c] = 0.5f * (ypv[c][j] - ymv[c][j]);
                // W-axis
                const float prev = (j > 0) ? pc[c][j - 1] : lo[c];
                const float next = (j < 3) ? pc[c][j + 1] : hi[c];
                if (w == 0)            gz[c] = pc[c][1] - pc[c][0];
                else if (w == WW - 1)  gz[c] = pc[c][3] - pc[c][2];
                else                   gz[c] = 0.5f * (next - prev);
            }
            const float dv  = gx[0] + gy[1] + gz[2];
            const float cxv = gz[1] - gy[2];
            const float cyv = gx[2] - gz[0];
            const float czv = gy[0] - gx[1];
            sum += dv * dv + sqrtf(cxv * cxv + cyv * cyv + czv * czv + 1e-8f);
        }

        // Rotate the register ring.
#pragma unroll
        for (int c = 0; c < 3; c++) {
#pragma unroll
            for (int k = 0; k < 4; k++) {
                pm[c][k] = pc[c][k];
                pc[c][k] = pp[c][k];
                pp[c][k] = nxt[c][k];
            }
        }
    }

    // Block reduction -> one double atomic per block.
#pragma unroll
    for (int o = 16; o > 0; o >>= 1)
        sum += __shfl_down_sync(FULL, sum, o);

    __shared__ float wsums[NTHREADS / 32];
    const int wid = tid >> 5;
    if (lane == 0) wsums[wid] = sum;
    __syncthreads();
    if (tid == 0) {
        float t = 0.0f;
#pragma unroll
        for (int k = 0; k < NTHREADS / 32; k++) t += wsums[k];
        atomicAdd(&g_acc, (double)t);
    }
}

extern "C" void kernel_launch(void* const* d_in, const int* in_sizes, int n_in,
                              void* d_out, int out_size) {
    const float* f = (const float*)d_in[0];
    float* out = (float*)d_out;
    (void)in_sizes; (void)n_in; (void)out_size;

    gcl_zero_kernel<<<1, 1>>>();
    dim3 grid(DD / XSEG, HH / Y_TILE, NB);   // 16 x 24 x 2 = 768 blocks
    dim3 block(BX, Y_TILE);                  // 48 x 8 = 384 threads
    gcl_main_kernel<<<grid, block>>>(f);
    gcl_finalize_kernel<<<1, 1>>>(out);
}